// round 2
// baseline (speedup 1.0000x reference)
#include <cuda_runtime.h>
#include <cstdint>
#include <cstddef>

// ============================================================================
// out = (q_lhs @ q_rhs) / (s_lhs * s_rhs), dynamic per-tensor symmetric int8.
// lhs, rhs: [4096,4096] f32. out: [4096,4096] f32.
// Engine: mma.sync m16n8k32 s8 (IMMA) — plain sm_103 target rejects tcgen05.
// ============================================================================

#define MDIM 4096
#define NDIM 4096
#define KDIM 4096

// -------------------- device scratch (no allocation allowed) ---------------
__device__ unsigned int g_absmax[2];
__device__ signed char g_qA[(size_t)MDIM * KDIM];   // lhs quantized, [M,K] K-major
__device__ signed char g_qB[(size_t)NDIM * KDIM];   // rhs^T quantized, [N,K] K-major

// -------------------- small helpers -----------------------------------------
__device__ __forceinline__ uint32_t smem_u32(const void* p) {
    uint32_t a;
    asm("{ .reg .u64 t; cvta.to.shared.u64 t, %1; cvt.u32.u64 %0, t; }" : "=r"(a) : "l"(p));
    return a;
}

__device__ __forceinline__ void cp_async16(uint32_t dst, const void* src) {
    asm volatile("cp.async.cg.shared.global [%0], [%1], 16;" :: "r"(dst), "l"(src) : "memory");
}
#define CP_COMMIT() asm volatile("cp.async.commit_group;" ::: "memory")
#define CP_WAIT2()  asm volatile("cp.async.wait_group 2;"  ::: "memory")

__device__ __forceinline__ void ldmx4(uint32_t& r0, uint32_t& r1, uint32_t& r2, uint32_t& r3,
                                      uint32_t addr) {
    asm volatile("ldmatrix.sync.aligned.m8n8.x4.shared.b16 {%0,%1,%2,%3}, [%4];"
                 : "=r"(r0), "=r"(r1), "=r"(r2), "=r"(r3) : "r"(addr));
}

__device__ __forceinline__ void imma16832(int* c, const uint32_t* a, const uint32_t* b) {
    asm volatile(
        "mma.sync.aligned.m16n8k32.row.col.s32.s8.s8.s32 "
        "{%0,%1,%2,%3}, {%4,%5,%6,%7}, {%8,%9}, {%0,%1,%2,%3};"
        : "+r"(c[0]), "+r"(c[1]), "+r"(c[2]), "+r"(c[3])
        : "r"(a[0]), "r"(a[1]), "r"(a[2]), "r"(a[3]), "r"(b[0]), "r"(b[1]));
}

// ============================================================================
// Kernel 0: reset absmax accumulators (graph replay determinism)
// ============================================================================
__global__ void init_kernel() {
    if (threadIdx.x < 2) g_absmax[threadIdx.x] = 0u;
}

// ============================================================================
// Kernel 1: per-tensor absmax (exact; atomicMax on positive float bits)
// ============================================================================
__global__ void absmax_kernel(const float4* __restrict__ x, int n4, int slot) {
    float m = 0.0f;
    for (int i = blockIdx.x * blockDim.x + threadIdx.x; i < n4; i += gridDim.x * blockDim.x) {
        float4 v = x[i];
        m = fmaxf(m, fmaxf(fmaxf(fabsf(v.x), fabsf(v.y)), fmaxf(fabsf(v.z), fabsf(v.w))));
    }
    #pragma unroll
    for (int o = 16; o; o >>= 1) m = fmaxf(m, __shfl_xor_sync(0xFFFFFFFFu, m, o));
    __shared__ float sm[8];
    if ((threadIdx.x & 31) == 0) sm[threadIdx.x >> 5] = m;
    __syncthreads();
    if (threadIdx.x == 0) {
        float bm = sm[0];
        #pragma unroll
        for (int i = 1; i < 8; i++) bm = fmaxf(bm, sm[i]);
        atomicMax(&g_absmax[slot], __float_as_uint(bm));
    }
}

// ============================================================================
// Kernel 2: quantize lhs -> g_qA [M,K]
// ============================================================================
__device__ __forceinline__ signed char quant1(float x, float s) {
    return (signed char)(int)fminf(fmaxf(rintf(x * s), -127.0f), 127.0f);
}

__global__ void quantA_kernel(const float4* __restrict__ lhs) {
    const int n4 = (MDIM * KDIM) / 4;
    float bound = fmaxf(__uint_as_float(g_absmax[0]), 1e-6f);
    float s = 127.0f / bound;
    char4* q = reinterpret_cast<char4*>(g_qA);
    for (int i = blockIdx.x * blockDim.x + threadIdx.x; i < n4; i += gridDim.x * blockDim.x) {
        float4 v = lhs[i];
        char4 c;
        c.x = quant1(v.x, s); c.y = quant1(v.y, s); c.z = quant1(v.z, s); c.w = quant1(v.w, s);
        q[i] = c;
    }
}

// ============================================================================
// Kernel 3: quantize + transpose rhs [K,N] -> g_qB [N,K]
// ============================================================================
__global__ void quantBT_kernel(const float* __restrict__ rhs) {
    __shared__ float tile[32][33];
    int n0 = blockIdx.x * 32;
    int k0 = blockIdx.y * 32;
    int tx = threadIdx.x;
    int ty = threadIdx.y;
    float bound = fmaxf(__uint_as_float(g_absmax[1]), 1e-6f);
    float s = 127.0f / bound;

    #pragma unroll
    for (int i = 0; i < 4; i++) {
        int k = ty + i * 8;
        tile[k][tx] = rhs[(size_t)(k0 + k) * NDIM + n0 + tx];
    }
    __syncthreads();

    int lin = ty * 32 + tx;
    int nl  = lin >> 3;
    int kc  = lin & 7;
    char4 c;
    c.x = quant1(tile[kc * 4 + 0][nl], s);
    c.y = quant1(tile[kc * 4 + 1][nl], s);
    c.z = quant1(tile[kc * 4 + 2][nl], s);
    c.w = quant1(tile[kc * 4 + 3][nl], s);
    *reinterpret_cast<char4*>(&g_qB[(size_t)(n0 + nl) * KDIM + k0 + kc * 4]) = c;
}

// ============================================================================
// Kernel 4: int8 IMMA GEMM. CTA 128x128, K-stage 64, 4-stage cp.async pipeline.
// 8 warps as 2(M) x 4(N); warp tile 64x32; mma.sync m16n8k32 s8s8s32.
// smem chunk swizzle: 16B chunk index c16 ^= (row>>1)&3 -> conflict-free ldmatrix.
// ============================================================================
#define TILE_M 128
#define TILE_N 128
#define KS     64
#define STAGES 4
#define NKT    (KDIM / KS)                // 64 stages of K
#define A_ST_BYTES (TILE_M * KS)          // 8192
#define B_ST_BYTES (TILE_N * KS)          // 8192
#define SMEM_B_OFF (STAGES * A_ST_BYTES)  // 32768
#define SMEM_TOTAL (STAGES * (A_ST_BYTES + B_ST_BYTES))   // 65536

__device__ __forceinline__ uint32_t swz_off(int row, int c16) {
    return (uint32_t)(row * 64 + ((c16 ^ ((row >> 1) & 3)) << 4));
}

__device__ __forceinline__ void load_stage(uint32_t sb, int tid, int st, int ks,
                                           const signed char* gA, const signed char* gB) {
    const signed char* ga = gA + (size_t)ks * KS;
    const signed char* gb = gB + (size_t)ks * KS;
    uint32_t ab = sb + st * A_ST_BYTES;
    uint32_t bb = sb + SMEM_B_OFF + st * B_ST_BYTES;
    #pragma unroll
    for (int i = 0; i < 2; i++) {
        int idx = tid + i * 256;
        int row = idx >> 2, c16 = idx & 3;
        cp_async16(ab + swz_off(row, c16), ga + (size_t)row * KDIM + c16 * 16);
    }
    #pragma unroll
    for (int i = 0; i < 2; i++) {
        int idx = tid + i * 256;
        int row = idx >> 2, c16 = idx & 3;
        cp_async16(bb + swz_off(row, c16), gb + (size_t)row * KDIM + c16 * 16);
    }
}

__global__ void __launch_bounds__(256) qgemm_kernel(float* __restrict__ out) {
    extern __shared__ char smem[];
    uint32_t sb = smem_u32(smem);
    int tid  = threadIdx.x;
    int wid  = tid >> 5;
    int lane = tid & 31;
    int wm = wid >> 2;          // 0..1
    int wn = wid & 3;           // 0..3
    int m0 = blockIdx.y * TILE_M;
    int n0 = blockIdx.x * TILE_N;

    const signed char* gA = g_qA + (size_t)m0 * KDIM;
    const signed char* gB = g_qB + (size_t)n0 * KDIM;

    int c[4][4][4];
    #pragma unroll
    for (int f = 0; f < 4; f++)
        #pragma unroll
        for (int j = 0; j < 4; j++)
            #pragma unroll
            for (int q = 0; q < 4; q++) c[f][j][q] = 0;

    // lane-invariant pieces of ldmatrix addressing
    int a_row_l = lane & 15;                 // row within 16-row frag
    int a_chalf = lane >> 4;                 // 0/1 -> low/high 16B of k32
    int b_row_l = ((lane >> 4) << 3) + (lane & 7);   // row within 16-row pair
    int b_chalf = (lane >> 3) & 1;

    // prologue: prefetch stages 0..2
    #pragma unroll
    for (int j = 0; j < STAGES - 1; j++) {
        load_stage(sb, tid, j, j, gA, gB);
        CP_COMMIT();
    }

    for (int ks = 0; ks < NKT; ks++) {
        int st = ks & (STAGES - 1);
        CP_WAIT2();
        __syncthreads();

        uint32_t ab = sb + st * A_ST_BYTES;
        uint32_t bb = sb + SMEM_B_OFF + st * B_ST_BYTES;

        #pragma unroll
        for (int kb = 0; kb < 2; kb++) {
            uint32_t a[4][4];
            uint32_t b[4][2];
            #pragma unroll
            for (int f = 0; f < 4; f++) {
                int row = wm * 64 + f * 16 + a_row_l;
                int c16 = 2 * kb + a_chalf;
                ldmx4(a[f][0], a[f][1], a[f][2], a[f][3], ab + swz_off(row, c16));
            }
            #pragma unroll
            for (int p = 0; p < 2; p++) {
                int row = wn * 32 + p * 16 + b_row_l;
                int c16 = 2 * kb + b_chalf;
                ldmx4(b[2 * p][0], b[2 * p][1], b[2 * p + 1][0], b[2 * p + 1][1],
                      bb + swz_off(row, c16));
            }
            #pragma unroll
            for (int f = 0; f < 4; f++)
                #pragma unroll
                for (int j = 0; j < 4; j++)
                    imma16832(c[f][j], a[f], b[j]);
        }

        int jn = ks + STAGES - 1;
        if (jn < NKT) {
            load_stage(sb, tid, jn & (STAGES - 1), jn, gA, gB);
        }
        CP_COMMIT();
    }

    // ------------------------- epilogue -------------------------------------
    float bl = fmaxf(__uint_as_float(g_absmax[0]), 1e-6f);
    float br = fmaxf(__uint_as_float(g_absmax[1]), 1e-6f);
    float factor = bl * br * (1.0f / (127.0f * 127.0f));

    int g   = lane >> 2;
    int tig = lane & 3;
    #pragma unroll
    for (int f = 0; f < 4; f++) {
        int row0 = m0 + wm * 64 + f * 16 + g;
        #pragma unroll
        for (int j = 0; j < 4; j++) {
            int col = n0 + wn * 32 + j * 8 + tig * 2;
            float2 v0, v1;
            v0.x = (float)c[f][j][0] * factor;
            v0.y = (float)c[f][j][1] * factor;
            v1.x = (float)c[f][j][2] * factor;
            v1.y = (float)c[f][j][3] * factor;
            *reinterpret_cast<float2*>(out + (size_t)row0 * NDIM + col)       = v0;
            *reinterpret_cast<float2*>(out + (size_t)(row0 + 8) * NDIM + col) = v1;
        }
    }
}

// ============================================================================
// Launch
// ============================================================================
extern "C" void kernel_launch(void* const* d_in, const int* in_sizes, int n_in,
                              void* d_out, int out_size) {
    const float* lhs = (const float*)d_in[0];
    const float* rhs = (const float*)d_in[1];
    float* out = (float*)d_out;

    cudaFuncSetAttribute(qgemm_kernel, cudaFuncAttributeMaxDynamicSharedMemorySize, SMEM_TOTAL);

    init_kernel<<<1, 32>>>();

    const int n4 = (MDIM * KDIM) / 4;
    absmax_kernel<<<512, 256>>>((const float4*)lhs, n4, 0);
    absmax_kernel<<<512, 256>>>((const float4*)rhs, n4, 1);

    quantA_kernel<<<2048, 256>>>((const float4*)lhs);

    dim3 tgrid(NDIM / 32, KDIM / 32);
    dim3 tblk(32, 8);
    quantBT_kernel<<<tgrid, tblk>>>(rhs);

    dim3 ggrid(NDIM / TILE_N, MDIM / TILE_M);   // (32, 32)
    qgemm_kernel<<<ggrid, 256, SMEM_TOTAL>>>(out);
}

// round 4
// speedup vs baseline: 1.0574x; 1.0574x over previous
#include <cuda_runtime.h>
#include <cstdint>
#include <cstddef>

// ============================================================================
// out = (q_lhs @ q_rhs) / (s_lhs * s_rhs), dynamic per-tensor symmetric int8.
// lhs, rhs: [4096,4096] f32. out: [4096,4096] f32.
// Engine: mma.sync m16n8k32 s8 (IMMA); tcgen05 rejected by sm_103 ptxas target.
// R4: fix R3 syntax (stage counter instead of ternary chain). Same design:
// 2 CTAs/SM (3-stage, 96KB smem, <=128 regs), K-stage 128, fewer barriers.
// ============================================================================

#define MDIM 4096
#define NDIM 4096
#define KDIM 4096

// -------------------- device scratch (no allocation allowed) ---------------
__device__ unsigned int g_absmax[2];
__device__ signed char g_qA[(size_t)MDIM * KDIM];   // lhs quantized, [M,K] K-major
__device__ signed char g_qB[(size_t)NDIM * KDIM];   // rhs^T quantized, [N,K] K-major

// -------------------- small helpers -----------------------------------------
__device__ __forceinline__ uint32_t smem_u32(const void* p) {
    uint32_t a;
    asm("{ .reg .u64 t; cvta.to.shared.u64 t, %1; cvt.u32.u64 %0, t; }" : "=r"(a) : "l"(p));
    return a;
}

__device__ __forceinline__ void cp_async16(uint32_t dst, const void* src) {
    asm volatile("cp.async.cg.shared.global [%0], [%1], 16;" :: "r"(dst), "l"(src) : "memory");
}
#define CP_COMMIT() asm volatile("cp.async.commit_group;" ::: "memory")
#define CP_WAIT1()  asm volatile("cp.async.wait_group 1;"  ::: "memory")

__device__ __forceinline__ void ldmx4(uint32_t& r0, uint32_t& r1, uint32_t& r2, uint32_t& r3,
                                      uint32_t addr) {
    asm volatile("ldmatrix.sync.aligned.m8n8.x4.shared.b16 {%0,%1,%2,%3}, [%4];"
                 : "=r"(r0), "=r"(r1), "=r"(r2), "=r"(r3) : "r"(addr));
}

__device__ __forceinline__ void imma16832(int* c, const uint32_t* a, const uint32_t* b) {
    asm volatile(
        "mma.sync.aligned.m16n8k32.row.col.s32.s8.s8.s32 "
        "{%0,%1,%2,%3}, {%4,%5,%6,%7}, {%8,%9}, {%0,%1,%2,%3};"
        : "+r"(c[0]), "+r"(c[1]), "+r"(c[2]), "+r"(c[3])
        : "r"(a[0]), "r"(a[1]), "r"(a[2]), "r"(a[3]), "r"(b[0]), "r"(b[1]));
}

// ============================================================================
// Kernel 0: reset absmax accumulators (graph replay determinism)
// ============================================================================
__global__ void init_kernel() {
    if (threadIdx.x < 2) g_absmax[threadIdx.x] = 0u;
}

// ============================================================================
// Kernel 1: per-tensor absmax (exact; atomicMax on positive float bits)
// ============================================================================
__global__ void absmax_kernel(const float4* __restrict__ x, int n4, int slot) {
    float m = 0.0f;
    for (int i = blockIdx.x * blockDim.x + threadIdx.x; i < n4; i += gridDim.x * blockDim.x) {
        float4 v = x[i];
        m = fmaxf(m, fmaxf(fmaxf(fabsf(v.x), fabsf(v.y)), fmaxf(fabsf(v.z), fabsf(v.w))));
    }
    #pragma unroll
    for (int o = 16; o; o >>= 1) m = fmaxf(m, __shfl_xor_sync(0xFFFFFFFFu, m, o));
    __shared__ float sm[8];
    if ((threadIdx.x & 31) == 0) sm[threadIdx.x >> 5] = m;
    __syncthreads();
    if (threadIdx.x == 0) {
        float bm = sm[0];
        #pragma unroll
        for (int i = 1; i < 8; i++) bm = fmaxf(bm, sm[i]);
        atomicMax(&g_absmax[slot], __float_as_uint(bm));
    }
}

// ============================================================================
// Kernel 2: quantize lhs -> g_qA [M,K]
// ============================================================================
__device__ __forceinline__ signed char quant1(float x, float s) {
    return (signed char)(int)fminf(fmaxf(rintf(x * s), -127.0f), 127.0f);
}

__global__ void quantA_kernel(const float4* __restrict__ lhs) {
    const int n4 = (MDIM * KDIM) / 4;
    float bound = fmaxf(__uint_as_float(g_absmax[0]), 1e-6f);
    float s = 127.0f / bound;
    char4* q = reinterpret_cast<char4*>(g_qA);
    for (int i = blockIdx.x * blockDim.x + threadIdx.x; i < n4; i += gridDim.x * blockDim.x) {
        float4 v = lhs[i];
        char4 c;
        c.x = quant1(v.x, s); c.y = quant1(v.y, s); c.z = quant1(v.z, s); c.w = quant1(v.w, s);
        q[i] = c;
    }
}

// ============================================================================
// Kernel 3: quantize + transpose rhs [K,N] -> g_qB [N,K]
// ============================================================================
__global__ void quantBT_kernel(const float* __restrict__ rhs) {
    __shared__ float tile[32][33];
    int n0 = blockIdx.x * 32;
    int k0 = blockIdx.y * 32;
    int tx = threadIdx.x;
    int ty = threadIdx.y;
    float bound = fmaxf(__uint_as_float(g_absmax[1]), 1e-6f);
    float s = 127.0f / bound;

    #pragma unroll
    for (int i = 0; i < 4; i++) {
        int k = ty + i * 8;
        tile[k][tx] = rhs[(size_t)(k0 + k) * NDIM + n0 + tx];
    }
    __syncthreads();

    int lin = ty * 32 + tx;
    int nl  = lin >> 3;
    int kc  = lin & 7;
    char4 c;
    c.x = quant1(tile[kc * 4 + 0][nl], s);
    c.y = quant1(tile[kc * 4 + 1][nl], s);
    c.z = quant1(tile[kc * 4 + 2][nl], s);
    c.w = quant1(tile[kc * 4 + 3][nl], s);
    *reinterpret_cast<char4*>(&g_qB[(size_t)(n0 + nl) * KDIM + k0 + kc * 4]) = c;
}

// ============================================================================
// Kernel 4: int8 IMMA GEMM. CTA 128x128, K-stage 128, 3-stage cp.async pipe,
// 2 CTAs/SM. 8 warps as 2(M) x 4(N); warp tile 64x32; m16n8k32 s8s8s32.
// smem rows are 128B; SW128 swizzle: c16' = c16 ^ (row & 7) -> conflict-free.
// ============================================================================
#define TILE_M 128
#define TILE_N 128
#define KS     128
#define STAGES 3
#define NKT    (KDIM / KS)                // 32
#define A_ST_BYTES (TILE_M * KS)          // 16384
#define B_ST_BYTES (TILE_N * KS)          // 16384
#define SMEM_B_OFF (STAGES * A_ST_BYTES)  // 49152
#define SMEM_TOTAL (STAGES * (A_ST_BYTES + B_ST_BYTES))   // 98304

__device__ __forceinline__ uint32_t swz_off(int row, int c16) {
    return (uint32_t)(row * 128 + ((c16 ^ (row & 7)) << 4));
}

__device__ __forceinline__ void load_stage(uint32_t sb, int tid, int st, int ks,
                                           const signed char* gA, const signed char* gB) {
    const signed char* ga = gA + (size_t)ks * KS;
    const signed char* gb = gB + (size_t)ks * KS;
    uint32_t ab = sb + st * A_ST_BYTES;
    uint32_t bb = sb + SMEM_B_OFF + st * B_ST_BYTES;
    #pragma unroll
    for (int i = 0; i < 4; i++) {
        int idx = tid + i * 256;
        int row = idx >> 3, c16 = idx & 7;
        cp_async16(ab + swz_off(row, c16), ga + (size_t)row * KDIM + c16 * 16);
    }
    #pragma unroll
    for (int i = 0; i < 4; i++) {
        int idx = tid + i * 256;
        int row = idx >> 3, c16 = idx & 7;
        cp_async16(bb + swz_off(row, c16), gb + (size_t)row * KDIM + c16 * 16);
    }
}

__global__ void __launch_bounds__(256, 2) qgemm_kernel(float* __restrict__ out) {
    extern __shared__ char smem[];
    uint32_t sb = smem_u32(smem);
    int tid  = threadIdx.x;
    int wid  = tid >> 5;
    int lane = tid & 31;
    int wm = wid >> 2;          // 0..1
    int wn = wid & 3;           // 0..3
    int m0 = blockIdx.y * TILE_M;
    int n0 = blockIdx.x * TILE_N;

    const signed char* gA = g_qA + (size_t)m0 * KDIM;
    const signed char* gB = g_qB + (size_t)n0 * KDIM;

    int c[4][4][4];
    #pragma unroll
    for (int f = 0; f < 4; f++)
        #pragma unroll
        for (int j = 0; j < 4; j++)
            #pragma unroll
            for (int q = 0; q < 4; q++) c[f][j][q] = 0;

    // lane-invariant pieces of ldmatrix addressing (validated in round 2)
    int a_row_l = lane & 15;                       // row within 16-row frag
    int a_chalf = lane >> 4;                       // low/high 16B of k32
    int b_row_l = ((lane >> 4) << 3) + (lane & 7); // row within 16-row pair
    int b_chalf = (lane >> 3) & 1;

    // prologue: prefetch stages 0..1 (two groups)
    #pragma unroll
    for (int j = 0; j < STAGES - 1; j++) {
        load_stage(sb, tid, j, j, gA, gB);
        CP_COMMIT();
    }

    int st = 0;       // compute stage slot (= ks mod 3, carried)
    int st2 = 2;      // load stage slot (= (ks+2) mod 3, carried)
    for (int ks = 0; ks < NKT; ks++) {
        CP_WAIT1();               // stage ks resident
        __syncthreads();          // all warps done reading the slot being refilled

        // immediately refill the freed slot (k-tile ks+2) before compute
        int jn = ks + STAGES - 1;
        if (jn < NKT) {
            load_stage(sb, tid, st2, jn, gA, gB);
            CP_COMMIT();
        }

        uint32_t ab = sb + st * A_ST_BYTES;
        uint32_t bb = sb + SMEM_B_OFF + st * B_ST_BYTES;

        #pragma unroll
        for (int kb = 0; kb < 4; kb++) {
            uint32_t a[4][4];
            uint32_t b[4][2];
            #pragma unroll
            for (int f = 0; f < 4; f++) {
                int row = wm * 64 + f * 16 + a_row_l;
                int c16 = 2 * kb + a_chalf;
                ldmx4(a[f][0], a[f][1], a[f][2], a[f][3], ab + swz_off(row, c16));
            }
            #pragma unroll
            for (int p = 0; p < 2; p++) {
                int row = wn * 32 + p * 16 + b_row_l;
                int c16 = 2 * kb + b_chalf;
                ldmx4(b[2 * p][0], b[2 * p][1], b[2 * p + 1][0], b[2 * p + 1][1],
                      bb + swz_off(row, c16));
            }
            #pragma unroll
            for (int f = 0; f < 4; f++)
                #pragma unroll
                for (int j = 0; j < 4; j++)
                    imma16832(c[f][j], a[f], b[j]);
        }

        st++;  if (st  == STAGES) st  = 0;
        st2++; if (st2 == STAGES) st2 = 0;
    }

    // ------------------------- epilogue -------------------------------------
    float bl = fmaxf(__uint_as_float(g_absmax[0]), 1e-6f);
    float br = fmaxf(__uint_as_float(g_absmax[1]), 1e-6f);
    float factor = bl * br * (1.0f / (127.0f * 127.0f));

    int g   = lane >> 2;
    int tig = lane & 3;
    #pragma unroll
    for (int f = 0; f < 4; f++) {
        int row0 = m0 + wm * 64 + f * 16 + g;
        #pragma unroll
        for (int j = 0; j < 4; j++) {
            int col = n0 + wn * 32 + j * 8 + tig * 2;
            float2 v0, v1;
            v0.x = (float)c[f][j][0] * factor;
            v0.y = (float)c[f][j][1] * factor;
            v1.x = (float)c[f][j][2] * factor;
            v1.y = (float)c[f][j][3] * factor;
            *reinterpret_cast<float2*>(out + (size_t)row0 * NDIM + col)       = v0;
            *reinterpret_cast<float2*>(out + (size_t)(row0 + 8) * NDIM + col) = v1;
        }
    }
}

// ============================================================================
// Launch
// ============================================================================
extern "C" void kernel_launch(void* const* d_in, const int* in_sizes, int n_in,
                              void* d_out, int out_size) {
    const float* lhs = (const float*)d_in[0];
    const float* rhs = (const float*)d_in[1];
    float* out = (float*)d_out;

    cudaFuncSetAttribute(qgemm_kernel, cudaFuncAttributeMaxDynamicSharedMemorySize, SMEM_TOTAL);

    init_kernel<<<1, 32>>>();

    const int n4 = (MDIM * KDIM) / 4;
    absmax_kernel<<<512, 256>>>((const float4*)lhs, n4, 0);
    absmax_kernel<<<512, 256>>>((const float4*)rhs, n4, 1);

    quantA_kernel<<<2048, 256>>>((const float4*)lhs);

    dim3 tgrid(NDIM / 32, KDIM / 32);
    dim3 tblk(32, 8);
    quantBT_kernel<<<tgrid, tblk>>>(rhs);

    dim3 ggrid(NDIM / TILE_N, MDIM / TILE_M);   // (32, 32)
    qgemm_kernel<<<ggrid, 256, SMEM_TOTAL>>>(out);
}

// round 5
// speedup vs baseline: 1.3453x; 1.2723x over previous
#include <cuda_runtime.h>
#include <cuda_bf16.h>
#include <cstdint>
#include <cstddef>

// ============================================================================
// out = (q_lhs @ q_rhs) / (s_lhs * s_rhs), dynamic per-tensor symmetric int8.
// R5: engine A/B test. Rows [0,2048): int8 IMMA (proven, ~270 MACs/cyc/SM).
// Rows [2048,4096): bf16 HMMA (quantized ints are exact in bf16; fp32 accum).
// Total time reveals the legacy HMMA rate vs legacy IMMA rate on sm_103.
// ============================================================================

#define MDIM 4096
#define NDIM 4096
#define KDIM 4096

// -------------------- device scratch (no allocation allowed) ---------------
__device__ unsigned int g_absmax[2];
__device__ signed char    g_qA[(size_t)MDIM * KDIM];   // lhs quantized s8, [M,K]
__device__ signed char    g_qB[(size_t)NDIM * KDIM];   // rhs^T quantized s8, [N,K]
__device__ __nv_bfloat16  g_hA[(size_t)MDIM * KDIM];   // lhs quantized bf16, [M,K]
__device__ __nv_bfloat16  g_hB[(size_t)NDIM * KDIM];   // rhs^T quantized bf16, [N,K]

// -------------------- small helpers -----------------------------------------
__device__ __forceinline__ uint32_t smem_u32(const void* p) {
    uint32_t a;
    asm("{ .reg .u64 t; cvta.to.shared.u64 t, %1; cvt.u32.u64 %0, t; }" : "=r"(a) : "l"(p));
    return a;
}

__device__ __forceinline__ void cp_async16(uint32_t dst, const void* src) {
    asm volatile("cp.async.cg.shared.global [%0], [%1], 16;" :: "r"(dst), "l"(src) : "memory");
}
#define CP_COMMIT() asm volatile("cp.async.commit_group;" ::: "memory")
#define CP_WAIT1()  asm volatile("cp.async.wait_group 1;"  ::: "memory")

__device__ __forceinline__ void ldmx4(uint32_t& r0, uint32_t& r1, uint32_t& r2, uint32_t& r3,
                                      uint32_t addr) {
    asm volatile("ldmatrix.sync.aligned.m8n8.x4.shared.b16 {%0,%1,%2,%3}, [%4];"
                 : "=r"(r0), "=r"(r1), "=r"(r2), "=r"(r3) : "r"(addr));
}

__device__ __forceinline__ void imma16832(int* c, const uint32_t* a, const uint32_t* b) {
    asm volatile(
        "mma.sync.aligned.m16n8k32.row.col.s32.s8.s8.s32 "
        "{%0,%1,%2,%3}, {%4,%5,%6,%7}, {%8,%9}, {%0,%1,%2,%3};"
        : "+r"(c[0]), "+r"(c[1]), "+r"(c[2]), "+r"(c[3])
        : "r"(a[0]), "r"(a[1]), "r"(a[2]), "r"(a[3]), "r"(b[0]), "r"(b[1]));
}

__device__ __forceinline__ void hmma16816(float* c, const uint32_t* a, const uint32_t* b) {
    asm volatile(
        "mma.sync.aligned.m16n8k16.row.col.f32.bf16.bf16.f32 "
        "{%0,%1,%2,%3}, {%4,%5,%6,%7}, {%8,%9}, {%0,%1,%2,%3};"
        : "+f"(c[0]), "+f"(c[1]), "+f"(c[2]), "+f"(c[3])
        : "r"(a[0]), "r"(a[1]), "r"(a[2]), "r"(a[3]), "r"(b[0]), "r"(b[1]));
}

// ============================================================================
// Kernel 0: reset absmax accumulators (graph replay determinism)
// ============================================================================
__global__ void init_kernel() {
    if (threadIdx.x < 2) g_absmax[threadIdx.x] = 0u;
}

// ============================================================================
// Kernel 1: per-tensor absmax (exact; atomicMax on positive float bits)
// ============================================================================
__global__ void absmax_kernel(const float4* __restrict__ x, int n4, int slot) {
    float m = 0.0f;
    for (int i = blockIdx.x * blockDim.x + threadIdx.x; i < n4; i += gridDim.x * blockDim.x) {
        float4 v = x[i];
        m = fmaxf(m, fmaxf(fmaxf(fabsf(v.x), fabsf(v.y)), fmaxf(fabsf(v.z), fabsf(v.w))));
    }
    #pragma unroll
    for (int o = 16; o; o >>= 1) m = fmaxf(m, __shfl_xor_sync(0xFFFFFFFFu, m, o));
    __shared__ float sm[8];
    if ((threadIdx.x & 31) == 0) sm[threadIdx.x >> 5] = m;
    __syncthreads();
    if (threadIdx.x == 0) {
        float bm = sm[0];
        #pragma unroll
        for (int i = 1; i < 8; i++) bm = fmaxf(bm, sm[i]);
        atomicMax(&g_absmax[slot], __float_as_uint(bm));
    }
}

// ============================================================================
// Kernel 2: quantize lhs -> g_qA (s8) and g_hA (bf16)
// ============================================================================
__device__ __forceinline__ float quantf(float x, float s) {
    return fminf(fmaxf(rintf(x * s), -127.0f), 127.0f);
}

__global__ void quantA_kernel(const float4* __restrict__ lhs) {
    const int n4 = (MDIM * KDIM) / 4;
    float bound = fmaxf(__uint_as_float(g_absmax[0]), 1e-6f);
    float s = 127.0f / bound;
    char4* q = reinterpret_cast<char4*>(g_qA);
    __nv_bfloat162* h = reinterpret_cast<__nv_bfloat162*>(g_hA);
    for (int i = blockIdx.x * blockDim.x + threadIdx.x; i < n4; i += gridDim.x * blockDim.x) {
        float4 v = lhs[i];
        float qx = quantf(v.x, s), qy = quantf(v.y, s);
        float qz = quantf(v.z, s), qw = quantf(v.w, s);
        char4 c;
        c.x = (signed char)(int)qx; c.y = (signed char)(int)qy;
        c.z = (signed char)(int)qz; c.w = (signed char)(int)qw;
        q[i] = c;
        h[2 * i]     = __floats2bfloat162_rn(qx, qy);
        h[2 * i + 1] = __floats2bfloat162_rn(qz, qw);
    }
}

// ============================================================================
// Kernel 3: quantize + transpose rhs [K,N] -> g_qB / g_hB [N,K]
// ============================================================================
__global__ void quantBT_kernel(const float* __restrict__ rhs) {
    __shared__ float tile[32][33];
    int n0 = blockIdx.x * 32;
    int k0 = blockIdx.y * 32;
    int tx = threadIdx.x;
    int ty = threadIdx.y;
    float bound = fmaxf(__uint_as_float(g_absmax[1]), 1e-6f);
    float s = 127.0f / bound;

    #pragma unroll
    for (int i = 0; i < 4; i++) {
        int k = ty + i * 8;
        tile[k][tx] = rhs[(size_t)(k0 + k) * NDIM + n0 + tx];
    }
    __syncthreads();

    int lin = ty * 32 + tx;
    int nl  = lin >> 3;
    int kc  = lin & 7;
    float q0 = quantf(tile[kc * 4 + 0][nl], s);
    float q1 = quantf(tile[kc * 4 + 1][nl], s);
    float q2 = quantf(tile[kc * 4 + 2][nl], s);
    float q3 = quantf(tile[kc * 4 + 3][nl], s);
    char4 c;
    c.x = (signed char)(int)q0; c.y = (signed char)(int)q1;
    c.z = (signed char)(int)q2; c.w = (signed char)(int)q3;
    size_t base = (size_t)(n0 + nl) * KDIM + k0 + kc * 4;
    *reinterpret_cast<char4*>(&g_qB[base]) = c;
    __nv_bfloat162* hb = reinterpret_cast<__nv_bfloat162*>(&g_hB[base]);
    hb[0] = __floats2bfloat162_rn(q0, q1);
    hb[1] = __floats2bfloat162_rn(q2, q3);
}

// ============================================================================
// Shared GEMM geometry: CTA 128x128, 3-stage cp.async, 2 CTAs/SM.
// 8 warps 2(M)x4(N), warp tile 64x32. 128B smem rows, swizzle c16^=(row&7).
// ============================================================================
#define TILE_M 128
#define TILE_N 128
#define STAGES 3
#define ST_BYTES 16384                       // 128 rows x 128B, per operand per stage
#define SMEM_B_OFF (STAGES * ST_BYTES)       // 49152
#define SMEM_TOTAL (2 * STAGES * ST_BYTES)   // 98304

__device__ __forceinline__ uint32_t swz_off(int row, int c16) {
    return (uint32_t)(row * 128 + ((c16 ^ (row & 7)) << 4));
}

// Load one 128x128-byte tile pair. ga/gb point at the k-tile start (byte ptrs),
// row stride in bytes given by rstride.
__device__ __forceinline__ void load_stage_b(uint32_t sb, int tid, int st,
                                             const char* ga, const char* gb, size_t rstride) {
    uint32_t ab = sb + st * ST_BYTES;
    uint32_t bb = sb + SMEM_B_OFF + st * ST_BYTES;
    #pragma unroll
    for (int i = 0; i < 4; i++) {
        int idx = tid + i * 256;
        int row = idx >> 3, c16 = idx & 7;
        cp_async16(ab + swz_off(row, c16), ga + (size_t)row * rstride + c16 * 16);
    }
    #pragma unroll
    for (int i = 0; i < 4; i++) {
        int idx = tid + i * 256;
        int row = idx >> 3, c16 = idx & 7;
        cp_async16(bb + swz_off(row, c16), gb + (size_t)row * rstride + c16 * 16);
    }
}

// ============================================================================
// Kernel 4a: int8 IMMA GEMM (rows [0, 2048)) — K-stage 128 bytes = 128 k.
// ============================================================================
#define NKT_I (KDIM / 128)      // 32

__global__ void __launch_bounds__(256, 2) qgemm_imma(float* __restrict__ out) {
    extern __shared__ char smem[];
    uint32_t sb = smem_u32(smem);
    int tid  = threadIdx.x;
    int wid  = tid >> 5;
    int lane = tid & 31;
    int wm = wid >> 2;
    int wn = wid & 3;
    int m0 = blockIdx.y * TILE_M;
    int n0 = blockIdx.x * TILE_N;

    const char* gA = (const char*)g_qA + (size_t)m0 * KDIM;
    const char* gB = (const char*)g_qB + (size_t)n0 * KDIM;

    int c[4][4][4];
    #pragma unroll
    for (int f = 0; f < 4; f++)
        #pragma unroll
        for (int j = 0; j < 4; j++)
            #pragma unroll
            for (int q = 0; q < 4; q++) c[f][j][q] = 0;

    int a_row_l = lane & 15;
    int a_chalf = lane >> 4;
    int b_row_l = ((lane >> 4) << 3) + (lane & 7);
    int b_chalf = (lane >> 3) & 1;

    #pragma unroll
    for (int j = 0; j < STAGES - 1; j++) {
        load_stage_b(sb, tid, j, gA + (size_t)j * 128, gB + (size_t)j * 128, KDIM);
        CP_COMMIT();
    }

    int st = 0, st2 = 2;
    for (int ks = 0; ks < NKT_I; ks++) {
        CP_WAIT1();
        __syncthreads();

        int jn = ks + STAGES - 1;
        if (jn < NKT_I) {
            load_stage_b(sb, tid, st2, gA + (size_t)jn * 128, gB + (size_t)jn * 128, KDIM);
            CP_COMMIT();
        }

        uint32_t ab = sb + st * ST_BYTES;
        uint32_t bb = sb + SMEM_B_OFF + st * ST_BYTES;

        #pragma unroll
        for (int kb = 0; kb < 4; kb++) {
            uint32_t a[4][4];
            uint32_t b[4][2];
            #pragma unroll
            for (int f = 0; f < 4; f++) {
                int row = wm * 64 + f * 16 + a_row_l;
                ldmx4(a[f][0], a[f][1], a[f][2], a[f][3], ab + swz_off(row, 2 * kb + a_chalf));
            }
            #pragma unroll
            for (int p = 0; p < 2; p++) {
                int row = wn * 32 + p * 16 + b_row_l;
                ldmx4(b[2 * p][0], b[2 * p][1], b[2 * p + 1][0], b[2 * p + 1][1],
                      bb + swz_off(row, 2 * kb + b_chalf));
            }
            #pragma unroll
            for (int f = 0; f < 4; f++)
                #pragma unroll
                for (int j = 0; j < 4; j++)
                    imma16832(c[f][j], a[f], b[j]);
        }

        st++;  if (st  == STAGES) st  = 0;
        st2++; if (st2 == STAGES) st2 = 0;
    }

    float bl = fmaxf(__uint_as_float(g_absmax[0]), 1e-6f);
    float br = fmaxf(__uint_as_float(g_absmax[1]), 1e-6f);
    float factor = bl * br * (1.0f / (127.0f * 127.0f));

    int g   = lane >> 2;
    int tig = lane & 3;
    #pragma unroll
    for (int f = 0; f < 4; f++) {
        int row0 = m0 + wm * 64 + f * 16 + g;
        #pragma unroll
        for (int j = 0; j < 4; j++) {
            int col = n0 + wn * 32 + j * 8 + tig * 2;
            float2 v0, v1;
            v0.x = (float)c[f][j][0] * factor;
            v0.y = (float)c[f][j][1] * factor;
            v1.x = (float)c[f][j][2] * factor;
            v1.y = (float)c[f][j][3] * factor;
            *reinterpret_cast<float2*>(out + (size_t)row0 * NDIM + col)       = v0;
            *reinterpret_cast<float2*>(out + (size_t)(row0 + 8) * NDIM + col) = v1;
        }
    }
}

// ============================================================================
// Kernel 4b: bf16 HMMA GEMM (rows [2048, 4096)) — K-stage 128 bytes = 64 k.
// Same smem/swizzle/fragment maps (byte-identical); mma is m16n8k16 bf16/f32.
// ============================================================================
#define NKT_H (KDIM / 64)       // 64

__global__ void __launch_bounds__(256, 2) qgemm_hmma(float* __restrict__ out) {
    extern __shared__ char smem[];
    uint32_t sb = smem_u32(smem);
    int tid  = threadIdx.x;
    int wid  = tid >> 5;
    int lane = tid & 31;
    int wm = wid >> 2;
    int wn = wid & 3;
    int m0 = 2048 + blockIdx.y * TILE_M;
    int n0 = blockIdx.x * TILE_N;

    const char* gA = (const char*)g_hA + (size_t)m0 * KDIM * 2;
    const char* gB = (const char*)g_hB + (size_t)n0 * KDIM * 2;
    const size_t rstride = (size_t)KDIM * 2;

    float c[4][4][4];
    #pragma unroll
    for (int f = 0; f < 4; f++)
        #pragma unroll
        for (int j = 0; j < 4; j++)
            #pragma unroll
            for (int q = 0; q < 4; q++) c[f][j][q] = 0.0f;

    int a_row_l = lane & 15;
    int a_chalf = lane >> 4;
    int b_row_l = ((lane >> 4) << 3) + (lane & 7);
    int b_chalf = (lane >> 3) & 1;

    #pragma unroll
    for (int j = 0; j < STAGES - 1; j++) {
        load_stage_b(sb, tid, j, gA + (size_t)j * 128, gB + (size_t)j * 128, rstride);
        CP_COMMIT();
    }

    int st = 0, st2 = 2;
    for (int ks = 0; ks < NKT_H; ks++) {
        CP_WAIT1();
        __syncthreads();

        int jn = ks + STAGES - 1;
        if (jn < NKT_H) {
            load_stage_b(sb, tid, st2, gA + (size_t)jn * 128, gB + (size_t)jn * 128, rstride);
            CP_COMMIT();
        }

        uint32_t ab = sb + st * ST_BYTES;
        uint32_t bb = sb + SMEM_B_OFF + st * ST_BYTES;

        #pragma unroll
        for (int kb = 0; kb < 4; kb++) {       // kb indexes k16 (32B) within the 128B tile
            uint32_t a[4][4];
            uint32_t b[4][2];
            #pragma unroll
            for (int f = 0; f < 4; f++) {
                int row = wm * 64 + f * 16 + a_row_l;
                ldmx4(a[f][0], a[f][1], a[f][2], a[f][3], ab + swz_off(row, 2 * kb + a_chalf));
            }
            #pragma unroll
            for (int p = 0; p < 2; p++) {
                int row = wn * 32 + p * 16 + b_row_l;
                ldmx4(b[2 * p][0], b[2 * p][1], b[2 * p + 1][0], b[2 * p + 1][1],
                      bb + swz_off(row, 2 * kb + b_chalf));
            }
            #pragma unroll
            for (int f = 0; f < 4; f++)
                #pragma unroll
                for (int j = 0; j < 4; j++)
                    hmma16816(c[f][j], a[f], b[j]);
        }

        st++;  if (st  == STAGES) st  = 0;
        st2++; if (st2 == STAGES) st2 = 0;
    }

    float bl = fmaxf(__uint_as_float(g_absmax[0]), 1e-6f);
    float br = fmaxf(__uint_as_float(g_absmax[1]), 1e-6f);
    float factor = bl * br * (1.0f / (127.0f * 127.0f));

    int g   = lane >> 2;
    int tig = lane & 3;
    #pragma unroll
    for (int f = 0; f < 4; f++) {
        int row0 = m0 + wm * 64 + f * 16 + g;
        #pragma unroll
        for (int j = 0; j < 4; j++) {
            int col = n0 + wn * 32 + j * 8 + tig * 2;
            float2 v0, v1;
            v0.x = c[f][j][0] * factor;
            v0.y = c[f][j][1] * factor;
            v1.x = c[f][j][2] * factor;
            v1.y = c[f][j][3] * factor;
            *reinterpret_cast<float2*>(out + (size_t)row0 * NDIM + col)       = v0;
            *reinterpret_cast<float2*>(out + (size_t)(row0 + 8) * NDIM + col) = v1;
        }
    }
}

// ============================================================================
// Launch
// ============================================================================
extern "C" void kernel_launch(void* const* d_in, const int* in_sizes, int n_in,
                              void* d_out, int out_size) {
    const float* lhs = (const float*)d_in[0];
    const float* rhs = (const float*)d_in[1];
    float* out = (float*)d_out;

    cudaFuncSetAttribute(qgemm_imma, cudaFuncAttributeMaxDynamicSharedMemorySize, SMEM_TOTAL);
    cudaFuncSetAttribute(qgemm_hmma, cudaFuncAttributeMaxDynamicSharedMemorySize, SMEM_TOTAL);

    init_kernel<<<1, 32>>>();

    const int n4 = (MDIM * KDIM) / 4;
    absmax_kernel<<<512, 256>>>((const float4*)lhs, n4, 0);
    absmax_kernel<<<512, 256>>>((const float4*)rhs, n4, 1);

    quantA_kernel<<<2048, 256>>>((const float4*)lhs);

    dim3 tgrid(NDIM / 32, KDIM / 32);
    dim3 tblk(32, 8);
    quantBT_kernel<<<tgrid, tblk>>>(rhs);

    dim3 ggrid(NDIM / TILE_N, (MDIM / 2) / TILE_M);   // (32, 16) each half
    qgemm_imma<<<ggrid, 256, SMEM_TOTAL>>>(out);
    qgemm_hmma<<<ggrid, 256, SMEM_TOTAL>>>(out);
}

// round 6
// speedup vs baseline: 2.7525x; 2.0460x over previous
#include <cuda_runtime.h>
#include <cuda_bf16.h>
#include <cstdint>
#include <cstddef>

// ============================================================================
// out = (q_lhs @ q_rhs) / (s_lhs * s_rhs), dynamic per-tensor symmetric int8.
// R6: full bf16 HMMA engine (A/B in R5 measured HMMA = 2.0x IMMA on sm_103's
// legacy mma.sync path; quantized ints are exact in bf16, fp32 accumulate).
// Pipeline: absmax -> quantize to bf16 (values in [-127,127]) -> HMMA GEMM
// -> scale by bound_l*bound_r/127^2.
// ============================================================================

#define MDIM 4096
#define NDIM 4096
#define KDIM 4096

// -------------------- device scratch (no allocation allowed) ---------------
__device__ unsigned int g_absmax[2];
__device__ __nv_bfloat16 g_hA[(size_t)MDIM * KDIM];   // lhs quantized bf16, [M,K]
__device__ __nv_bfloat16 g_hB[(size_t)NDIM * KDIM];   // rhs^T quantized bf16, [N,K]

// -------------------- small helpers -----------------------------------------
__device__ __forceinline__ uint32_t smem_u32(const void* p) {
    uint32_t a;
    asm("{ .reg .u64 t; cvta.to.shared.u64 t, %1; cvt.u32.u64 %0, t; }" : "=r"(a) : "l"(p));
    return a;
}

__device__ __forceinline__ void cp_async16(uint32_t dst, const void* src) {
    asm volatile("cp.async.cg.shared.global [%0], [%1], 16;" :: "r"(dst), "l"(src) : "memory");
}
#define CP_COMMIT() asm volatile("cp.async.commit_group;" ::: "memory")
#define CP_WAIT1()  asm volatile("cp.async.wait_group 1;"  ::: "memory")

__device__ __forceinline__ void ldmx4(uint32_t& r0, uint32_t& r1, uint32_t& r2, uint32_t& r3,
                                      uint32_t addr) {
    asm volatile("ldmatrix.sync.aligned.m8n8.x4.shared.b16 {%0,%1,%2,%3}, [%4];"
                 : "=r"(r0), "=r"(r1), "=r"(r2), "=r"(r3) : "r"(addr));
}

__device__ __forceinline__ void hmma16816(float* c, const uint32_t* a, const uint32_t* b) {
    asm volatile(
        "mma.sync.aligned.m16n8k16.row.col.f32.bf16.bf16.f32 "
        "{%0,%1,%2,%3}, {%4,%5,%6,%7}, {%8,%9}, {%0,%1,%2,%3};"
        : "+f"(c[0]), "+f"(c[1]), "+f"(c[2]), "+f"(c[3])
        : "r"(a[0]), "r"(a[1]), "r"(a[2]), "r"(a[3]), "r"(b[0]), "r"(b[1]));
}

// ============================================================================
// Kernel 0: reset absmax accumulators (graph replay determinism)
// ============================================================================
__global__ void init_kernel() {
    if (threadIdx.x < 2) g_absmax[threadIdx.x] = 0u;
}

// ============================================================================
// Kernel 1: per-tensor absmax (exact; atomicMax on positive float bits)
// ============================================================================
__global__ void absmax_kernel(const float4* __restrict__ x, int n4, int slot) {
    float m = 0.0f;
    for (int i = blockIdx.x * blockDim.x + threadIdx.x; i < n4; i += gridDim.x * blockDim.x) {
        float4 v = x[i];
        m = fmaxf(m, fmaxf(fmaxf(fabsf(v.x), fabsf(v.y)), fmaxf(fabsf(v.z), fabsf(v.w))));
    }
    #pragma unroll
    for (int o = 16; o; o >>= 1) m = fmaxf(m, __shfl_xor_sync(0xFFFFFFFFu, m, o));
    __shared__ float sm[8];
    if ((threadIdx.x & 31) == 0) sm[threadIdx.x >> 5] = m;
    __syncthreads();
    if (threadIdx.x == 0) {
        float bm = sm[0];
        #pragma unroll
        for (int i = 1; i < 8; i++) bm = fmaxf(bm, sm[i]);
        atomicMax(&g_absmax[slot], __float_as_uint(bm));
    }
}

// ============================================================================
// Kernel 2: quantize lhs -> g_hA (bf16, integer-valued in [-127,127])
// ============================================================================
__device__ __forceinline__ float quantf(float x, float s) {
    return fminf(fmaxf(rintf(x * s), -127.0f), 127.0f);
}

__global__ void quantA_kernel(const float4* __restrict__ lhs) {
    const int n4 = (MDIM * KDIM) / 4;
    float bound = fmaxf(__uint_as_float(g_absmax[0]), 1e-6f);
    float s = 127.0f / bound;
    __nv_bfloat162* h = reinterpret_cast<__nv_bfloat162*>(g_hA);
    for (int i = blockIdx.x * blockDim.x + threadIdx.x; i < n4; i += gridDim.x * blockDim.x) {
        float4 v = lhs[i];
        h[2 * i]     = __floats2bfloat162_rn(quantf(v.x, s), quantf(v.y, s));
        h[2 * i + 1] = __floats2bfloat162_rn(quantf(v.z, s), quantf(v.w, s));
    }
}

// ============================================================================
// Kernel 3: quantize + transpose rhs [K,N] -> g_hB [N,K]
// ============================================================================
__global__ void quantBT_kernel(const float* __restrict__ rhs) {
    __shared__ float tile[32][33];
    int n0 = blockIdx.x * 32;
    int k0 = blockIdx.y * 32;
    int tx = threadIdx.x;
    int ty = threadIdx.y;
    float bound = fmaxf(__uint_as_float(g_absmax[1]), 1e-6f);
    float s = 127.0f / bound;

    #pragma unroll
    for (int i = 0; i < 4; i++) {
        int k = ty + i * 8;
        tile[k][tx] = rhs[(size_t)(k0 + k) * NDIM + n0 + tx];
    }
    __syncthreads();

    int lin = ty * 32 + tx;
    int nl  = lin >> 3;
    int kc  = lin & 7;
    size_t base = (size_t)(n0 + nl) * KDIM + k0 + kc * 4;
    __nv_bfloat162* hb = reinterpret_cast<__nv_bfloat162*>(&g_hB[base]);
    hb[0] = __floats2bfloat162_rn(quantf(tile[kc * 4 + 0][nl], s),
                                  quantf(tile[kc * 4 + 1][nl], s));
    hb[1] = __floats2bfloat162_rn(quantf(tile[kc * 4 + 2][nl], s),
                                  quantf(tile[kc * 4 + 3][nl], s));
}

// ============================================================================
// Kernel 4: bf16 HMMA GEMM. CTA 128x128, K-stage 64 (128B rows), 3-stage
// cp.async pipe, 2 CTAs/SM. 8 warps 2(M)x4(N), warp tile 64x32.
// smem swizzle c16^=(row&7); fragment maps validated (byte-identical to R2).
// ============================================================================
#define TILE_M 128
#define TILE_N 128
#define STAGES 3
#define ST_BYTES 16384                       // 128 rows x 128B
#define SMEM_B_OFF (STAGES * ST_BYTES)       // 49152
#define SMEM_TOTAL (2 * STAGES * ST_BYTES)   // 98304
#define NKT (KDIM / 64)                      // 64 k-tiles of 64 k-elems (128B)

__device__ __forceinline__ uint32_t swz_off(int row, int c16) {
    return (uint32_t)(row * 128 + ((c16 ^ (row & 7)) << 4));
}

__device__ __forceinline__ void load_stage_b(uint32_t sb, int tid, int st,
                                             const char* ga, const char* gb, size_t rstride) {
    uint32_t ab = sb + st * ST_BYTES;
    uint32_t bb = sb + SMEM_B_OFF + st * ST_BYTES;
    #pragma unroll
    for (int i = 0; i < 4; i++) {
        int idx = tid + i * 256;
        int row = idx >> 3, c16 = idx & 7;
        cp_async16(ab + swz_off(row, c16), ga + (size_t)row * rstride + c16 * 16);
    }
    #pragma unroll
    for (int i = 0; i < 4; i++) {
        int idx = tid + i * 256;
        int row = idx >> 3, c16 = idx & 7;
        cp_async16(bb + swz_off(row, c16), gb + (size_t)row * rstride + c16 * 16);
    }
}

__global__ void __launch_bounds__(256, 2) qgemm_hmma(float* __restrict__ out) {
    extern __shared__ char smem[];
    uint32_t sb = smem_u32(smem);
    int tid  = threadIdx.x;
    int wid  = tid >> 5;
    int lane = tid & 31;
    int wm = wid >> 2;
    int wn = wid & 3;
    int m0 = blockIdx.y * TILE_M;
    int n0 = blockIdx.x * TILE_N;

    const char* gA = (const char*)g_hA + (size_t)m0 * KDIM * 2;
    const char* gB = (const char*)g_hB + (size_t)n0 * KDIM * 2;
    const size_t rstride = (size_t)KDIM * 2;

    float c[4][4][4];
    #pragma unroll
    for (int f = 0; f < 4; f++)
        #pragma unroll
        for (int j = 0; j < 4; j++)
            #pragma unroll
            for (int q = 0; q < 4; q++) c[f][j][q] = 0.0f;

    int a_row_l = lane & 15;
    int a_chalf = lane >> 4;
    int b_row_l = ((lane >> 4) << 3) + (lane & 7);
    int b_chalf = (lane >> 3) & 1;

    #pragma unroll
    for (int j = 0; j < STAGES - 1; j++) {
        load_stage_b(sb, tid, j, gA + (size_t)j * 128, gB + (size_t)j * 128, rstride);
        CP_COMMIT();
    }

    int st = 0, st2 = 2;
    for (int ks = 0; ks < NKT; ks++) {
        CP_WAIT1();
        __syncthreads();

        int jn = ks + STAGES - 1;
        if (jn < NKT) {
            load_stage_b(sb, tid, st2, gA + (size_t)jn * 128, gB + (size_t)jn * 128, rstride);
            CP_COMMIT();
        }

        uint32_t ab = sb + st * ST_BYTES;
        uint32_t bb = sb + SMEM_B_OFF + st * ST_BYTES;

        #pragma unroll
        for (int kb = 0; kb < 4; kb++) {      // 4 x k16 per 128B stage
            uint32_t a[4][4];
            uint32_t b[4][2];
            #pragma unroll
            for (int f = 0; f < 4; f++) {
                int row = wm * 64 + f * 16 + a_row_l;
                ldmx4(a[f][0], a[f][1], a[f][2], a[f][3], ab + swz_off(row, 2 * kb + a_chalf));
            }
            #pragma unroll
            for (int p = 0; p < 2; p++) {
                int row = wn * 32 + p * 16 + b_row_l;
                ldmx4(b[2 * p][0], b[2 * p][1], b[2 * p + 1][0], b[2 * p + 1][1],
                      bb + swz_off(row, 2 * kb + b_chalf));
            }
            #pragma unroll
            for (int f = 0; f < 4; f++)
                #pragma unroll
                for (int j = 0; j < 4; j++)
                    hmma16816(c[f][j], a[f], b[j]);
        }

        st++;  if (st  == STAGES) st  = 0;
        st2++; if (st2 == STAGES) st2 = 0;
    }

    float bl = fmaxf(__uint_as_float(g_absmax[0]), 1e-6f);
    float br = fmaxf(__uint_as_float(g_absmax[1]), 1e-6f);
    float factor = bl * br * (1.0f / (127.0f * 127.0f));

    int g   = lane >> 2;
    int tig = lane & 3;
    #pragma unroll
    for (int f = 0; f < 4; f++) {
        int row0 = m0 + wm * 64 + f * 16 + g;
        #pragma unroll
        for (int j = 0; j < 4; j++) {
            int col = n0 + wn * 32 + j * 8 + tig * 2;
            float2 v0, v1;
            v0.x = c[f][j][0] * factor;
            v0.y = c[f][j][1] * factor;
            v1.x = c[f][j][2] * factor;
            v1.y = c[f][j][3] * factor;
            *reinterpret_cast<float2*>(out + (size_t)row0 * NDIM + col)       = v0;
            *reinterpret_cast<float2*>(out + (size_t)(row0 + 8) * NDIM + col) = v1;
        }
    }
}

// ============================================================================
// Launch
// ============================================================================
extern "C" void kernel_launch(void* const* d_in, const int* in_sizes, int n_in,
                              void* d_out, int out_size) {
    const float* lhs = (const float*)d_in[0];
    const float* rhs = (const float*)d_in[1];
    float* out = (float*)d_out;

    cudaFuncSetAttribute(qgemm_hmma, cudaFuncAttributeMaxDynamicSharedMemorySize, SMEM_TOTAL);

    init_kernel<<<1, 32>>>();

    const int n4 = (MDIM * KDIM) / 4;
    absmax_kernel<<<512, 256>>>((const float4*)lhs, n4, 0);
    absmax_kernel<<<512, 256>>>((const float4*)rhs, n4, 1);

    quantA_kernel<<<2048, 256>>>((const float4*)lhs);

    dim3 tgrid(NDIM / 32, KDIM / 32);
    dim3 tblk(32, 8);
    quantBT_kernel<<<tgrid, tblk>>>(rhs);

    dim3 ggrid(NDIM / TILE_N, MDIM / TILE_M);   // (32, 32)
    qgemm_hmma<<<ggrid, 256, SMEM_TOTAL>>>(out);
}

// round 7
// speedup vs baseline: 2.8595x; 1.0389x over previous
#include <cuda_runtime.h>
#include <cuda_bf16.h>
#include <cstdint>
#include <cstddef>

// ============================================================================
// out = (q_lhs @ q_rhs) / (s_lhs * s_rhs), dynamic per-tensor symmetric int8.
// R7: bf16 HMMA engine (validated, ~300us). Preprocessing overhaul:
//  - fused absmax over both tensors in one wave-balanced launch
//  - quantBT: 64x64 tiles, float4 loads, 16B vector stores
// ============================================================================

#define MDIM 4096
#define NDIM 4096
#define KDIM 4096

// -------------------- device scratch (no allocation allowed) ---------------
__device__ unsigned int g_absmax[2];
__device__ __nv_bfloat16 g_hA[(size_t)MDIM * KDIM];   // lhs quantized bf16, [M,K]
__device__ __nv_bfloat16 g_hB[(size_t)NDIM * KDIM];   // rhs^T quantized bf16, [N,K]

// -------------------- small helpers -----------------------------------------
__device__ __forceinline__ uint32_t smem_u32(const void* p) {
    uint32_t a;
    asm("{ .reg .u64 t; cvta.to.shared.u64 t, %1; cvt.u32.u64 %0, t; }" : "=r"(a) : "l"(p));
    return a;
}

__device__ __forceinline__ void cp_async16(uint32_t dst, const void* src) {
    asm volatile("cp.async.cg.shared.global [%0], [%1], 16;" :: "r"(dst), "l"(src) : "memory");
}
#define CP_COMMIT() asm volatile("cp.async.commit_group;" ::: "memory")
#define CP_WAIT1()  asm volatile("cp.async.wait_group 1;"  ::: "memory")

__device__ __forceinline__ void ldmx4(uint32_t& r0, uint32_t& r1, uint32_t& r2, uint32_t& r3,
                                      uint32_t addr) {
    asm volatile("ldmatrix.sync.aligned.m8n8.x4.shared.b16 {%0,%1,%2,%3}, [%4];"
                 : "=r"(r0), "=r"(r1), "=r"(r2), "=r"(r3) : "r"(addr));
}

__device__ __forceinline__ void hmma16816(float* c, const uint32_t* a, const uint32_t* b) {
    asm volatile(
        "mma.sync.aligned.m16n8k16.row.col.f32.bf16.bf16.f32 "
        "{%0,%1,%2,%3}, {%4,%5,%6,%7}, {%8,%9}, {%0,%1,%2,%3};"
        : "+f"(c[0]), "+f"(c[1]), "+f"(c[2]), "+f"(c[3])
        : "r"(a[0]), "r"(a[1]), "r"(a[2]), "r"(a[3]), "r"(b[0]), "r"(b[1]));
}

// ============================================================================
// Kernel 0: reset absmax accumulators (graph replay determinism)
// ============================================================================
__global__ void init_kernel() {
    if (threadIdx.x < 2) g_absmax[threadIdx.x] = 0u;
}

// ============================================================================
// Kernel 1: fused per-tensor absmax for BOTH tensors, one launch.
// Blocks [0, half) scan lhs -> slot 0; [half, 2*half) scan rhs -> slot 1.
// ============================================================================
__global__ void absmax2_kernel(const float4* __restrict__ a,
                               const float4* __restrict__ b, int n4) {
    int half = gridDim.x >> 1;
    int slot = (blockIdx.x >= half) ? 1 : 0;
    const float4* x = slot ? b : a;
    int bid = blockIdx.x - slot * half;

    float m = 0.0f;
    for (int i = bid * blockDim.x + threadIdx.x; i < n4; i += half * blockDim.x) {
        float4 v = x[i];
        m = fmaxf(m, fmaxf(fmaxf(fabsf(v.x), fabsf(v.y)), fmaxf(fabsf(v.z), fabsf(v.w))));
    }
    #pragma unroll
    for (int o = 16; o; o >>= 1) m = fmaxf(m, __shfl_xor_sync(0xFFFFFFFFu, m, o));
    __shared__ float sm[8];
    if ((threadIdx.x & 31) == 0) sm[threadIdx.x >> 5] = m;
    __syncthreads();
    if (threadIdx.x == 0) {
        float bm = sm[0];
        #pragma unroll
        for (int i = 1; i < 8; i++) bm = fmaxf(bm, sm[i]);
        atomicMax(&g_absmax[slot], __float_as_uint(bm));
    }
}

// ============================================================================
// Kernel 2: quantize lhs -> g_hA (bf16, integer-valued in [-127,127])
// ============================================================================
__device__ __forceinline__ float quantf(float x, float s) {
    return fminf(fmaxf(rintf(x * s), -127.0f), 127.0f);
}

__global__ void quantA_kernel(const float4* __restrict__ lhs) {
    const int n4 = (MDIM * KDIM) / 4;
    float bound = fmaxf(__uint_as_float(g_absmax[0]), 1e-6f);
    float s = 127.0f / bound;
    __nv_bfloat162* h = reinterpret_cast<__nv_bfloat162*>(g_hA);
    for (int i = blockIdx.x * blockDim.x + threadIdx.x; i < n4; i += gridDim.x * blockDim.x) {
        float4 v = lhs[i];
        h[2 * i]     = __floats2bfloat162_rn(quantf(v.x, s), quantf(v.y, s));
        h[2 * i + 1] = __floats2bfloat162_rn(quantf(v.z, s), quantf(v.w, s));
    }
}

// ============================================================================
// Kernel 3: quantize + transpose rhs [K,N] -> g_hB [N,K].
// 64x64 tile per 256-thread block; float4 loads; 2x16B bf16 stores per thread.
// ============================================================================
__global__ void __launch_bounds__(256) quantBT_kernel(const float* __restrict__ rhs) {
    __shared__ float tile[64][65];
    int n0 = blockIdx.x * 64;
    int k0 = blockIdx.y * 64;
    int tid = threadIdx.x;
    float bound = fmaxf(__uint_as_float(g_absmax[1]), 1e-6f);
    float s = 127.0f / bound;

    // Load 64 rows (k) x 64 cols (n): 4 threads per row, 4 float4 each.
    {
        int row = tid >> 2;             // 0..63 (k within tile)
        int c4  = tid & 3;              // 0..3
        const float4* src = reinterpret_cast<const float4*>(
            rhs + (size_t)(k0 + row) * NDIM + n0);
        #pragma unroll
        for (int i = 0; i < 4; i++) {
            float4 v = src[c4 * 4 + i];
            int c = c4 * 16 + i * 4;
            tile[row][c + 0] = v.x;
            tile[row][c + 1] = v.y;
            tile[row][c + 2] = v.z;
            tile[row][c + 3] = v.w;
        }
    }
    __syncthreads();

    // Store: each thread emits 16 consecutive k for one n (32B = 2 x uint4).
    {
        int n  = tid >> 2;              // 0..63 (n within tile)
        int kc = tid & 3;               // 0..3 (16-k chunk)
        uint32_t packed[8];
        #pragma unroll
        for (int i = 0; i < 8; i++) {
            __nv_bfloat162 p = __floats2bfloat162_rn(
                quantf(tile[kc * 16 + 2 * i][n], s),
                quantf(tile[kc * 16 + 2 * i + 1][n], s));
            packed[i] = *reinterpret_cast<uint32_t*>(&p);
        }
        __nv_bfloat16* dst = g_hB + (size_t)(n0 + n) * KDIM + k0 + kc * 16;
        uint4* d4 = reinterpret_cast<uint4*>(dst);
        d4[0] = make_uint4(packed[0], packed[1], packed[2], packed[3]);
        d4[1] = make_uint4(packed[4], packed[5], packed[6], packed[7]);
    }
}

// ============================================================================
// Kernel 4: bf16 HMMA GEMM. CTA 128x128, K-stage 64 (128B rows), 3-stage
// cp.async pipe, 2 CTAs/SM. 8 warps 2(M)x4(N), warp tile 64x32. (validated)
// ============================================================================
#define TILE_M 128
#define TILE_N 128
#define STAGES 3
#define ST_BYTES 16384
#define SMEM_B_OFF (STAGES * ST_BYTES)
#define SMEM_TOTAL (2 * STAGES * ST_BYTES)
#define NKT (KDIM / 64)

__device__ __forceinline__ uint32_t swz_off(int row, int c16) {
    return (uint32_t)(row * 128 + ((c16 ^ (row & 7)) << 4));
}

__device__ __forceinline__ void load_stage_b(uint32_t sb, int tid, int st,
                                             const char* ga, const char* gb, size_t rstride) {
    uint32_t ab = sb + st * ST_BYTES;
    uint32_t bb = sb + SMEM_B_OFF + st * ST_BYTES;
    #pragma unroll
    for (int i = 0; i < 4; i++) {
        int idx = tid + i * 256;
        int row = idx >> 3, c16 = idx & 7;
        cp_async16(ab + swz_off(row, c16), ga + (size_t)row * rstride + c16 * 16);
    }
    #pragma unroll
    for (int i = 0; i < 4; i++) {
        int idx = tid + i * 256;
        int row = idx >> 3, c16 = idx & 7;
        cp_async16(bb + swz_off(row, c16), gb + (size_t)row * rstride + c16 * 16);
    }
}

__global__ void __launch_bounds__(256, 2) qgemm_hmma(float* __restrict__ out) {
    extern __shared__ char smem[];
    uint32_t sb = smem_u32(smem);
    int tid  = threadIdx.x;
    int wid  = tid >> 5;
    int lane = tid & 31;
    int wm = wid >> 2;
    int wn = wid & 3;
    int m0 = blockIdx.y * TILE_M;
    int n0 = blockIdx.x * TILE_N;

    const char* gA = (const char*)g_hA + (size_t)m0 * KDIM * 2;
    const char* gB = (const char*)g_hB + (size_t)n0 * KDIM * 2;
    const size_t rstride = (size_t)KDIM * 2;

    float c[4][4][4];
    #pragma unroll
    for (int f = 0; f < 4; f++)
        #pragma unroll
        for (int j = 0; j < 4; j++)
            #pragma unroll
            for (int q = 0; q < 4; q++) c[f][j][q] = 0.0f;

    int a_row_l = lane & 15;
    int a_chalf = lane >> 4;
    int b_row_l = ((lane >> 4) << 3) + (lane & 7);
    int b_chalf = (lane >> 3) & 1;

    #pragma unroll
    for (int j = 0; j < STAGES - 1; j++) {
        load_stage_b(sb, tid, j, gA + (size_t)j * 128, gB + (size_t)j * 128, rstride);
        CP_COMMIT();
    }

    int st = 0, st2 = 2;
    for (int ks = 0; ks < NKT; ks++) {
        CP_WAIT1();
        __syncthreads();

        int jn = ks + STAGES - 1;
        if (jn < NKT) {
            load_stage_b(sb, tid, st2, gA + (size_t)jn * 128, gB + (size_t)jn * 128, rstride);
            CP_COMMIT();
        }

        uint32_t ab = sb + st * ST_BYTES;
        uint32_t bb = sb + SMEM_B_OFF + st * ST_BYTES;

        #pragma unroll
        for (int kb = 0; kb < 4; kb++) {
            uint32_t a[4][4];
            uint32_t b[4][2];
            #pragma unroll
            for (int f = 0; f < 4; f++) {
                int row = wm * 64 + f * 16 + a_row_l;
                ldmx4(a[f][0], a[f][1], a[f][2], a[f][3], ab + swz_off(row, 2 * kb + a_chalf));
            }
            #pragma unroll
            for (int p = 0; p < 2; p++) {
                int row = wn * 32 + p * 16 + b_row_l;
                ldmx4(b[2 * p][0], b[2 * p][1], b[2 * p + 1][0], b[2 * p + 1][1],
                      bb + swz_off(row, 2 * kb + b_chalf));
            }
            #pragma unroll
            for (int f = 0; f < 4; f++)
                #pragma unroll
                for (int j = 0; j < 4; j++)
                    hmma16816(c[f][j], a[f], b[j]);
        }

        st++;  if (st  == STAGES) st  = 0;
        st2++; if (st2 == STAGES) st2 = 0;
    }

    float bl = fmaxf(__uint_as_float(g_absmax[0]), 1e-6f);
    float br = fmaxf(__uint_as_float(g_absmax[1]), 1e-6f);
    float factor = bl * br * (1.0f / (127.0f * 127.0f));

    int g   = lane >> 2;
    int tig = lane & 3;
    #pragma unroll
    for (int f = 0; f < 4; f++) {
        int row0 = m0 + wm * 64 + f * 16 + g;
        #pragma unroll
        for (int j = 0; j < 4; j++) {
            int col = n0 + wn * 32 + j * 8 + tig * 2;
            float2 v0, v1;
            v0.x = c[f][j][0] * factor;
            v0.y = c[f][j][1] * factor;
            v1.x = c[f][j][2] * factor;
            v1.y = c[f][j][3] * factor;
            *reinterpret_cast<float2*>(out + (size_t)row0 * NDIM + col)       = v0;
            *reinterpret_cast<float2*>(out + (size_t)(row0 + 8) * NDIM + col) = v1;
        }
    }
}

// ============================================================================
// Launch
// ============================================================================
extern "C" void kernel_launch(void* const* d_in, const int* in_sizes, int n_in,
                              void* d_out, int out_size) {
    const float* lhs = (const float*)d_in[0];
    const float* rhs = (const float*)d_in[1];
    float* out = (float*)d_out;

    cudaFuncSetAttribute(qgemm_hmma, cudaFuncAttributeMaxDynamicSharedMemorySize, SMEM_TOTAL);

    init_kernel<<<1, 32>>>();

    const int n4 = (MDIM * KDIM) / 4;
    absmax2_kernel<<<1184, 256>>>((const float4*)lhs, (const float4*)rhs, n4);

    quantA_kernel<<<2048, 256>>>((const float4*)lhs);

    dim3 tgrid(NDIM / 64, KDIM / 64);   // (64, 64)
    quantBT_kernel<<<tgrid, 256>>>(rhs);

    dim3 ggrid(NDIM / TILE_N, MDIM / TILE_M);   // (32, 32)
    qgemm_hmma<<<ggrid, 256, SMEM_TOTAL>>>(out);
}

// round 8
// speedup vs baseline: 2.9891x; 1.0453x over previous
#include <cuda_runtime.h>
#include <cuda_bf16.h>
#include <cstdint>
#include <cstddef>

// ============================================================================
// out = (q_lhs @ q_rhs) / (s_lhs * s_rhs), dynamic per-tensor symmetric int8.
// R8: quantBT conflict-free smem reads; init launch folded into GEMM-tail
// reset (atomic ticket); GEMM k-loop unrolled by 3 for static stage offsets.
// Engine: bf16 HMMA mma.sync (quantized ints exact in bf16, fp32 accum).
// ============================================================================

#define MDIM 4096
#define NDIM 4096
#define KDIM 4096

// -------------------- device scratch (no allocation allowed) ---------------
__device__ unsigned int g_absmax[2];    // zero-init; reset by last GEMM CTA
__device__ unsigned int g_done;         // ticket counter, reset likewise
__device__ __nv_bfloat16 g_hA[(size_t)MDIM * KDIM];   // lhs quantized bf16, [M,K]
__device__ __nv_bfloat16 g_hB[(size_t)NDIM * KDIM];   // rhs^T quantized bf16, [N,K]

// -------------------- small helpers -----------------------------------------
__device__ __forceinline__ uint32_t smem_u32(const void* p) {
    uint32_t a;
    asm("{ .reg .u64 t; cvta.to.shared.u64 t, %1; cvt.u32.u64 %0, t; }" : "=r"(a) : "l"(p));
    return a;
}

__device__ __forceinline__ void cp_async16(uint32_t dst, const void* src) {
    asm volatile("cp.async.cg.shared.global [%0], [%1], 16;" :: "r"(dst), "l"(src) : "memory");
}
#define CP_COMMIT() asm volatile("cp.async.commit_group;" ::: "memory")
#define CP_WAIT1()  asm volatile("cp.async.wait_group 1;"  ::: "memory")

__device__ __forceinline__ void ldmx4(uint32_t& r0, uint32_t& r1, uint32_t& r2, uint32_t& r3,
                                      uint32_t addr) {
    asm volatile("ldmatrix.sync.aligned.m8n8.x4.shared.b16 {%0,%1,%2,%3}, [%4];"
                 : "=r"(r0), "=r"(r1), "=r"(r2), "=r"(r3) : "r"(addr));
}

__device__ __forceinline__ void hmma16816(float* c, const uint32_t* a, const uint32_t* b) {
    asm volatile(
        "mma.sync.aligned.m16n8k16.row.col.f32.bf16.bf16.f32 "
        "{%0,%1,%2,%3}, {%4,%5,%6,%7}, {%8,%9}, {%0,%1,%2,%3};"
        : "+f"(c[0]), "+f"(c[1]), "+f"(c[2]), "+f"(c[3])
        : "r"(a[0]), "r"(a[1]), "r"(a[2]), "r"(a[3]), "r"(b[0]), "r"(b[1]));
}

// ============================================================================
// Kernel 1: fused per-tensor absmax for BOTH tensors, one launch.
// g_absmax starts at 0 (zero-init on first run, reset by GEMM tail after).
// ============================================================================
__global__ void absmax2_kernel(const float4* __restrict__ a,
                               const float4* __restrict__ b, int n4) {
    int half = gridDim.x >> 1;
    int slot = (blockIdx.x >= half) ? 1 : 0;
    const float4* x = slot ? b : a;
    int bid = blockIdx.x - slot * half;

    float m = 0.0f;
    for (int i = bid * blockDim.x + threadIdx.x; i < n4; i += half * blockDim.x) {
        float4 v = x[i];
        m = fmaxf(m, fmaxf(fmaxf(fabsf(v.x), fabsf(v.y)), fmaxf(fabsf(v.z), fabsf(v.w))));
    }
    #pragma unroll
    for (int o = 16; o; o >>= 1) m = fmaxf(m, __shfl_xor_sync(0xFFFFFFFFu, m, o));
    __shared__ float sm[8];
    if ((threadIdx.x & 31) == 0) sm[threadIdx.x >> 5] = m;
    __syncthreads();
    if (threadIdx.x == 0) {
        float bm = sm[0];
        #pragma unroll
        for (int i = 1; i < 8; i++) bm = fmaxf(bm, sm[i]);
        atomicMax(&g_absmax[slot], __float_as_uint(bm));
    }
}

// ============================================================================
// Kernel 2: quantize lhs -> g_hA (bf16, integer-valued in [-127,127])
// ============================================================================
__device__ __forceinline__ float quantf(float x, float s) {
    return fminf(fmaxf(rintf(x * s), -127.0f), 127.0f);
}

__global__ void quantA_kernel(const float4* __restrict__ lhs) {
    const int n4 = (MDIM * KDIM) / 4;
    float bound = fmaxf(__uint_as_float(g_absmax[0]), 1e-6f);
    float s = 127.0f / bound;
    __nv_bfloat162* h = reinterpret_cast<__nv_bfloat162*>(g_hA);
    for (int i = blockIdx.x * blockDim.x + threadIdx.x; i < n4; i += gridDim.x * blockDim.x) {
        float4 v = lhs[i];
        h[2 * i]     = __floats2bfloat162_rn(quantf(v.x, s), quantf(v.y, s));
        h[2 * i + 1] = __floats2bfloat162_rn(quantf(v.z, s), quantf(v.w, s));
    }
}

// ============================================================================
// Kernel 3: quantize + transpose rhs [K,N] -> g_hB [N,K].
// 64x64 tile per 256-thread block. Store phase: per warp, row fixed and n
// spans 32 consecutive values -> all 32 banks distinct, conflict-free reads.
// ============================================================================
__global__ void __launch_bounds__(256) quantBT_kernel(const float* __restrict__ rhs) {
    __shared__ float tile[64][65];
    int n0 = blockIdx.x * 64;
    int k0 = blockIdx.y * 64;
    int tid = threadIdx.x;
    float bound = fmaxf(__uint_as_float(g_absmax[1]), 1e-6f);
    float s = 127.0f / bound;

    // Load 64 rows (k) x 64 cols (n): 4 threads per row, 4 float4 each.
    {
        int row = tid >> 2;             // 0..63 (k within tile)
        int c4  = tid & 3;              // 0..3
        const float4* src = reinterpret_cast<const float4*>(
            rhs + (size_t)(k0 + row) * NDIM + n0);
        #pragma unroll
        for (int i = 0; i < 4; i++) {
            float4 v = src[c4 * 4 + i];
            int c = c4 * 16 + i * 4;
            tile[row][c + 0] = v.x;
            tile[row][c + 1] = v.y;
            tile[row][c + 2] = v.z;
            tile[row][c + 3] = v.w;
        }
    }
    __syncthreads();

    // Store: n = tid&63 (consecutive per warp), kc = tid>>6 (fixed per warp-pair).
    {
        int n  = tid & 63;
        int kc = tid >> 6;              // 0..3 (16-k chunk)
        uint32_t packed[8];
        #pragma unroll
        for (int i = 0; i < 8; i++) {
            __nv_bfloat162 p = __floats2bfloat162_rn(
                quantf(tile[kc * 16 + 2 * i][n], s),
                quantf(tile[kc * 16 + 2 * i + 1][n], s));
            packed[i] = *reinterpret_cast<uint32_t*>(&p);
        }
        __nv_bfloat16* dst = g_hB + (size_t)(n0 + n) * KDIM + k0 + kc * 16;
        uint4* d4 = reinterpret_cast<uint4*>(dst);
        d4[0] = make_uint4(packed[0], packed[1], packed[2], packed[3]);
        d4[1] = make_uint4(packed[4], packed[5], packed[6], packed[7]);
    }
}

// ============================================================================
// Kernel 4: bf16 HMMA GEMM. CTA 128x128, K-stage 64 (128B rows), 3-stage
// cp.async pipe, 2 CTAs/SM. 8 warps 2(M)x4(N), warp tile 64x32.
// k-loop unrolled by 3 so all stage offsets are compile-time constants.
// ============================================================================
#define TILE_M 128
#define TILE_N 128
#define STAGES 3
#define ST_BYTES 16384
#define SMEM_B_OFF (STAGES * ST_BYTES)
#define SMEM_TOTAL (2 * STAGES * ST_BYTES)
#define NKT (KDIM / 64)                 // 64

__device__ __forceinline__ uint32_t swz_off(int row, int c16) {
    return (uint32_t)(row * 128 + ((c16 ^ (row & 7)) << 4));
}

__device__ __forceinline__ void load_stage_b(uint32_t sb, int tid, int st,
                                             const char* ga, const char* gb, size_t rstride) {
    uint32_t ab = sb + st * ST_BYTES;
    uint32_t bb = sb + SMEM_B_OFF + st * ST_BYTES;
    #pragma unroll
    for (int i = 0; i < 4; i++) {
        int idx = tid + i * 256;
        int row = idx >> 3, c16 = idx & 7;
        cp_async16(ab + swz_off(row, c16), ga + (size_t)row * rstride + c16 * 16);
    }
    #pragma unroll
    for (int i = 0; i < 4; i++) {
        int idx = tid + i * 256;
        int row = idx >> 3, c16 = idx & 7;
        cp_async16(bb + swz_off(row, c16), gb + (size_t)row * rstride + c16 * 16);
    }
}

struct GemmCtx {
    uint32_t sb;
    int tid;
    const char* gA;
    const char* gB;
    int a_row_l, a_chalf, b_row_l, b_chalf, wm, wn;
};

// One k-tile iteration with compile-time stage slot ST.
template <int ST>
__device__ __forceinline__ void k_iter(const GemmCtx& x, int ks, float c[4][4][4]) {
    const size_t rstride = (size_t)KDIM * 2;
    CP_WAIT1();
    __syncthreads();

    int jn = ks + STAGES - 1;
    if (jn < NKT) {
        constexpr int ST2 = (ST + 2) % 3;
        load_stage_b(x.sb, x.tid, ST2, x.gA + (size_t)jn * 128, x.gB + (size_t)jn * 128, rstride);
        CP_COMMIT();
    }

    uint32_t ab = x.sb + ST * ST_BYTES;
    uint32_t bb = x.sb + SMEM_B_OFF + ST * ST_BYTES;

    #pragma unroll
    for (int kb = 0; kb < 4; kb++) {
        uint32_t a[4][4];
        uint32_t b[4][2];
        #pragma unroll
        for (int f = 0; f < 4; f++) {
            int row = x.wm * 64 + f * 16 + x.a_row_l;
            ldmx4(a[f][0], a[f][1], a[f][2], a[f][3], ab + swz_off(row, 2 * kb + x.a_chalf));
        }
        #pragma unroll
        for (int p = 0; p < 2; p++) {
            int row = x.wn * 32 + p * 16 + x.b_row_l;
            ldmx4(b[2 * p][0], b[2 * p][1], b[2 * p + 1][0], b[2 * p + 1][1],
                  bb + swz_off(row, 2 * kb + x.b_chalf));
        }
        #pragma unroll
        for (int f = 0; f < 4; f++)
            #pragma unroll
            for (int j = 0; j < 4; j++)
                hmma16816(c[f][j], a[f], b[j]);
    }
}

__global__ void __launch_bounds__(256, 2) qgemm_hmma(float* __restrict__ out) {
    extern __shared__ char smem[];
    GemmCtx x;
    x.sb  = smem_u32(smem);
    x.tid = threadIdx.x;
    int wid  = x.tid >> 5;
    int lane = x.tid & 31;
    x.wm = wid >> 2;
    x.wn = wid & 3;
    int m0 = blockIdx.y * TILE_M;
    int n0 = blockIdx.x * TILE_N;

    x.gA = (const char*)g_hA + (size_t)m0 * KDIM * 2;
    x.gB = (const char*)g_hB + (size_t)n0 * KDIM * 2;
    const size_t rstride = (size_t)KDIM * 2;

    float c[4][4][4];
    #pragma unroll
    for (int f = 0; f < 4; f++)
        #pragma unroll
        for (int j = 0; j < 4; j++)
            #pragma unroll
            for (int q = 0; q < 4; q++) c[f][j][q] = 0.0f;

    x.a_row_l = lane & 15;
    x.a_chalf = lane >> 4;
    x.b_row_l = ((lane >> 4) << 3) + (lane & 7);
    x.b_chalf = (lane >> 3) & 1;

    #pragma unroll
    for (int j = 0; j < STAGES - 1; j++) {
        load_stage_b(x.sb, x.tid, j, x.gA + (size_t)j * 128, x.gB + (size_t)j * 128, rstride);
        CP_COMMIT();
    }

    // 63 iterations in groups of 3 (static stages), then tail ks=63 (stage 0).
    int ks = 0;
    #pragma unroll 1
    for (int t = 0; t < 21; t++) {
        k_iter<0>(x, ks + 0, c);
        k_iter<1>(x, ks + 1, c);
        k_iter<2>(x, ks + 2, c);
        ks += 3;
    }
    k_iter<0>(x, 63, c);

    float bl = fmaxf(__uint_as_float(g_absmax[0]), 1e-6f);
    float br = fmaxf(__uint_as_float(g_absmax[1]), 1e-6f);
    float factor = bl * br * (1.0f / (127.0f * 127.0f));

    int g   = lane >> 2;
    int tig = lane & 3;
    #pragma unroll
    for (int f = 0; f < 4; f++) {
        int row0 = m0 + x.wm * 64 + f * 16 + g;
        #pragma unroll
        for (int j = 0; j < 4; j++) {
            int col = n0 + x.wn * 32 + j * 8 + tig * 2;
            float2 v0, v1;
            v0.x = c[f][j][0] * factor;
            v0.y = c[f][j][1] * factor;
            v1.x = c[f][j][2] * factor;
            v1.y = c[f][j][3] * factor;
            *reinterpret_cast<float2*>(out + (size_t)row0 * NDIM + col)       = v0;
            *reinterpret_cast<float2*>(out + (size_t)(row0 + 8) * NDIM + col) = v1;
        }
    }

    // Last CTA to finish resets scratch state for the next graph replay.
    __syncthreads();
    if (x.tid == 0) {
        __threadfence();
        unsigned int ticket = atomicInc(&g_done, 0xFFFFFFFFu);
        if (ticket == gridDim.x * gridDim.y - 1) {
            g_absmax[0] = 0u;
            g_absmax[1] = 0u;
            g_done = 0u;
            __threadfence();
        }
    }
}

// ============================================================================
// Launch
// ============================================================================
extern "C" void kernel_launch(void* const* d_in, const int* in_sizes, int n_in,
                              void* d_out, int out_size) {
    const float* lhs = (const float*)d_in[0];
    const float* rhs = (const float*)d_in[1];
    float* out = (float*)d_out;

    cudaFuncSetAttribute(qgemm_hmma, cudaFuncAttributeMaxDynamicSharedMemorySize, SMEM_TOTAL);

    const int n4 = (MDIM * KDIM) / 4;
    absmax2_kernel<<<1184, 256>>>((const float4*)lhs, (const float4*)rhs, n4);

    quantA_kernel<<<2048, 256>>>((const float4*)lhs);

    dim3 tgrid(NDIM / 64, KDIM / 64);   // (64, 64)
    quantBT_kernel<<<tgrid, 256>>>(rhs);

    dim3 ggrid(NDIM / TILE_N, MDIM / TILE_M);   // (32, 32)
    qgemm_hmma<<<ggrid, 256, SMEM_TOTAL>>>(out);
}